// round 1
// baseline (speedup 1.0000x reference)
#include <cuda_runtime.h>

// AdaptiveFeaturePooling: 4-level ROIAlign (out=14, sampling_ratio=2) + max over levels.
// Levels use cumulative scales: L3:224, L2:224*112, L1:...*56, L0:...*28.
// feats[l] is [1,256,H,W] with H=W=224>>l.  Output [R,256,14,14] fp32.

#define OUTSZ  14
#define CELLS  196          // 14*14
#define CH     256
#define SR     2
#define GSAMP  28           // OUTSZ*SR

__global__ __launch_bounds__(256)
void afp_kernel(const float* __restrict__ f0, const float* __restrict__ f1,
                const float* __restrict__ f2, const float* __restrict__ f3,
                const float* __restrict__ rois, float* __restrict__ out)
{
    // [level][axis(0=y,1=x)][sample]
    __shared__ int   s_lo[4][2][GSAMP];
    __shared__ int   s_hi[4][2][GSAMP];
    __shared__ float s_w0[4][2][GSAMP];   // (1-frac)*valid
    __shared__ float s_w1[4][2][GSAMP];   // frac*valid
    __shared__ unsigned char s_mask[CELLS]; // bit l => level l has a live tap

    const int r   = blockIdx.x;
    const int tid = threadIdx.x;

    // ---- Phase A: per-(level,axis,sample) bilinear prep (replicates reference fp32 order)
    if (tid < 4 * 2 * GSAMP) {
        int l   = tid / (2 * GSAMP);
        int rem = tid - l * (2 * GSAMP);
        int a   = rem / GSAMP;            // 0=y, 1=x
        int j   = rem - a * GSAMP;

        float p1 = rois[r * 4 + (a == 0 ? 1 : 0)];
        float p2 = rois[r * 4 + (a == 0 ? 3 : 2)];
        // cumulative scaling exactly as in reference: r *= (2^i * 28) for i = 3..l
        #pragma unroll
        for (int i = 3; i >= 0; --i) {
            if (i >= l) {
                float s = (float)(28 << i);
                p1 = __fmul_rn(p1, s);
                p2 = __fmul_rn(p2, s);
            }
        }
        float len  = fmaxf(__fadd_rn(p2, -p1), 1.0f);
        float t    = __fdiv_rn(len, 14.0f);
        float step = ((float)j + 0.5f) * 0.5f;               // exact
        float c    = __fadd_rn(p1, __fmul_rn(step, t));

        int L = 224 >> l;
        bool valid = (c >= -1.0f) && (c <= (float)L);
        c = fminf(fmaxf(c, 0.0f), (float)(L - 1));
        float lo   = floorf(c);
        float frac = __fadd_rn(c, -lo);
        int loi = (int)lo;
        int hii = loi + 1;
        if (loi >= L - 1) { loi = L - 1; hii = L - 1; frac = 0.0f; }
        float v = valid ? 1.0f : 0.0f;
        s_lo[l][a][j] = loi;
        s_hi[l][a][j] = hii;
        s_w0[l][a][j] = (1.0f - frac) * v;
        s_w1[l][a][j] = frac * v;
    }
    __syncthreads();

    // ---- Phase B: per-cell level-validity mask
    if (tid < CELLS) {
        int py = tid / OUTSZ;
        int px = tid - py * OUTSZ;
        unsigned m = 0;
        #pragma unroll
        for (int l = 0; l < 4; ++l) {
            float wy = s_w0[l][0][2*py]   + s_w1[l][0][2*py]
                     + s_w0[l][0][2*py+1] + s_w1[l][0][2*py+1];
            float wx = s_w0[l][1][2*px]   + s_w1[l][1][2*px]
                     + s_w0[l][1][2*px+1] + s_w1[l][1][2*px+1];
            if (wy > 0.0f && wx > 0.0f) m |= (1u << l);
        }
        s_mask[tid] = (unsigned char)m;
    }
    __syncthreads();

    const float* fl[4] = { f0, f1, f2, f3 };

    const size_t outBase = (size_t)r * (CH * CELLS);
    // ---- Phase C: each thread emits float4 groups (196 % 4 == 0 -> group stays in one channel)
    for (int g = tid; g < (CH * CELLS) / 4; g += 256) {
        int idx   = g * 4;
        int c     = idx / CELLS;
        int cell0 = idx - c * CELLS;
        uchar4 m4 = *reinterpret_cast<const uchar4*>(&s_mask[cell0]);
        unsigned mm[4] = { m4.x, m4.y, m4.z, m4.w };

        float res[4];
        #pragma unroll
        for (int q = 0; q < 4; ++q) {
            int cell = cell0 + q;
            float best = 0.0f;
            unsigned m = mm[q];
            if (m) {
                int py = cell / OUTSZ;
                int px = cell - py * OUTSZ;
                int sy = 2 * py, sx = 2 * px;
                float vlev[4];
                #pragma unroll
                for (int l = 0; l < 4; ++l) {
                    float val = 0.0f;
                    if (m & (1u << l)) {
                        int W = 224 >> l;
                        const float* fc = fl[l] + (size_t)c * (W * W);
                        float acc = 0.0f;
                        #pragma unroll
                        for (int dy = 0; dy < 2; ++dy) {
                            float wy0 = s_w0[l][0][sy + dy];
                            float wy1 = s_w1[l][0][sy + dy];
                            if (wy0 + wy1 > 0.0f) {
                                int y0 = s_lo[l][0][sy + dy];
                                int y1 = s_hi[l][0][sy + dy];
                                const float* row0 = fc + y0 * W;
                                const float* row1 = fc + y1 * W;
                                #pragma unroll
                                for (int dx = 0; dx < 2; ++dx) {
                                    float wx0 = s_w0[l][1][sx + dx];
                                    float wx1 = s_w1[l][1][sx + dx];
                                    if (wx0 + wx1 > 0.0f) {
                                        int x0 = s_lo[l][1][sx + dx];
                                        int x1 = s_hi[l][1][sx + dx];
                                        acc += wy0 * (wx0 * row0[x0] + wx1 * row0[x1])
                                             + wy1 * (wx0 * row1[x0] + wx1 * row1[x1]);
                                    }
                                }
                            }
                        }
                        val = acc * 0.25f;
                    }
                    vlev[l] = val;
                }
                best = fmaxf(fmaxf(vlev[0], vlev[1]), fmaxf(vlev[2], vlev[3]));
            }
            res[q] = best;
        }
        float4 o = make_float4(res[0], res[1], res[2], res[3]);
        *reinterpret_cast<float4*>(out + outBase + idx) = o;
    }
}

extern "C" void kernel_launch(void* const* d_in, const int* in_sizes, int n_in,
                              void* d_out, int out_size)
{
    const float* f0   = (const float*)d_in[0];
    const float* f1   = (const float*)d_in[1];
    const float* f2   = (const float*)d_in[2];
    const float* f3   = (const float*)d_in[3];
    const float* rois = (const float*)d_in[4];
    int R = in_sizes[4] / 4;
    afp_kernel<<<R, 256>>>(f0, f1, f2, f3, rois, (float*)d_out);
}

// round 2
// speedup vs baseline: 1.7798x; 1.7798x over previous
#include <cuda_runtime.h>

// AdaptiveFeaturePooling: 4-level ROIAlign (out=14, sr=2) + max over levels.
// Structure: per ROI, build bilinear tables (Phase A), compact list of cells
// with any live tap (Phase B, usually empty), then a tight coalesced zero-fill
// of the output slice followed by sparse recompute of the rare valid cells.

#define OUTSZ  14
#define CELLS  196
#define CH     256
#define CHB    128          // channels per block (grid.y = 2)
#define GSAMP  28           // OUTSZ*2

__global__ __launch_bounds__(256, 6)
void afp_kernel(const float* __restrict__ f0, const float* __restrict__ f1,
                const float* __restrict__ f2, const float* __restrict__ f3,
                const float* __restrict__ rois, float* __restrict__ out)
{
    __shared__ int   s_lo[4][2][GSAMP];
    __shared__ int   s_hi[4][2][GSAMP];
    __shared__ float s_w0[4][2][GSAMP];
    __shared__ float s_w1[4][2][GSAMP];
    __shared__ short s_vcell[CELLS];
    __shared__ unsigned char s_vmask[CELLS];
    __shared__ int s_nvalid;

    const int r   = blockIdx.x;
    const int by  = blockIdx.y;          // channel half
    const int tid = threadIdx.x;

    // ---- Phase A: bilinear prep, replicating reference fp32 op order exactly.
    if (tid < 4 * 2 * GSAMP) {
        int l   = tid / (2 * GSAMP);
        int rem = tid - l * (2 * GSAMP);
        int a   = rem / GSAMP;           // 0=y, 1=x
        int j   = rem - a * GSAMP;

        float p1 = rois[r * 4 + (a == 0 ? 1 : 0)];
        float p2 = rois[r * 4 + (a == 0 ? 3 : 2)];
        #pragma unroll
        for (int i = 3; i >= 0; --i) {
            if (i >= l) {
                float s = (float)(28 << i);
                p1 = __fmul_rn(p1, s);
                p2 = __fmul_rn(p2, s);
            }
        }
        float len  = fmaxf(__fadd_rn(p2, -p1), 1.0f);
        float t    = __fdiv_rn(len, 14.0f);
        float step = ((float)j + 0.5f) * 0.5f;
        float c    = __fadd_rn(p1, __fmul_rn(step, t));

        int L = 224 >> l;
        bool valid = (c >= -1.0f) && (c <= (float)L);
        c = fminf(fmaxf(c, 0.0f), (float)(L - 1));
        float lo   = floorf(c);
        float frac = __fadd_rn(c, -lo);
        int loi = (int)lo;
        int hii = loi + 1;
        if (loi >= L - 1) { loi = L - 1; hii = L - 1; frac = 0.0f; }
        float v = valid ? 1.0f : 0.0f;
        s_lo[l][a][j] = loi;
        s_hi[l][a][j] = hii;
        s_w0[l][a][j] = (1.0f - frac) * v;
        s_w1[l][a][j] = frac * v;
    }
    if (tid == 255) s_nvalid = 0;
    __syncthreads();

    // ---- Phase B: compact list of cells with any live level.
    if (tid < CELLS) {
        int py = tid / OUTSZ;
        int px = tid - py * OUTSZ;
        unsigned m = 0;
        #pragma unroll
        for (int l = 0; l < 4; ++l) {
            float wy = s_w0[l][0][2*py]   + s_w1[l][0][2*py]
                     + s_w0[l][0][2*py+1] + s_w1[l][0][2*py+1];
            float wx = s_w0[l][1][2*px]   + s_w1[l][1][2*px]
                     + s_w0[l][1][2*px+1] + s_w1[l][1][2*px+1];
            if (wy > 0.0f && wx > 0.0f) m |= (1u << l);
        }
        if (m) {
            int pos = atomicAdd(&s_nvalid, 1);
            s_vcell[pos] = (short)tid;
            s_vmask[pos] = (unsigned char)m;
        }
    }
    __syncthreads();

    // ---- Phase C1: tight coalesced zero-fill of this block's slice.
    const size_t base = (size_t)r * (CH * CELLS) + (size_t)by * (CHB * CELLS);
    {
        float4* o4 = reinterpret_cast<float4*>(out + base);
        const float4 z = make_float4(0.f, 0.f, 0.f, 0.f);
        #pragma unroll 4
        for (int g = tid; g < (CHB * CELLS) / 4; g += 256) o4[g] = z;
    }
    __syncthreads();   // order zero stores before sparse overwrites

    // ---- Phase C2: sparse recompute of valid cells (two cells per iteration).
    const int nv = s_nvalid;
    if (nv == 0) return;

    const float* fl[4] = { f0, f1, f2, f3 };
    const int cloc = tid & (CHB - 1);         // local channel 0..127
    const int cglb = by * CHB + cloc;         // global channel

    for (int vi = 0; vi < nv; vi += 2) {
        int v = vi + (tid >> 7);
        if (v < nv) {
            int cell = s_vcell[v];
            unsigned m = s_vmask[v];
            int py = cell / OUTSZ;
            int px = cell - py * OUTSZ;
            int sy = 2 * py, sx = 2 * px;

            float best = 0.0f;
            #pragma unroll
            for (int l = 0; l < 4; ++l) {
                float val = 0.0f;
                if (m & (1u << l)) {
                    int W = 224 >> l;
                    const float* fc = fl[l] + (size_t)cglb * (W * W);
                    float acc = 0.0f;
                    #pragma unroll
                    for (int dy = 0; dy < 2; ++dy) {
                        float wy0 = s_w0[l][0][sy + dy];
                        float wy1 = s_w1[l][0][sy + dy];
                        if (wy0 + wy1 > 0.0f) {
                            int y0 = s_lo[l][0][sy + dy];
                            int y1 = s_hi[l][0][sy + dy];
                            const float* row0 = fc + y0 * W;
                            const float* row1 = fc + y1 * W;
                            #pragma unroll
                            for (int dx = 0; dx < 2; ++dx) {
                                float wx0 = s_w0[l][1][sx + dx];
                                float wx1 = s_w1[l][1][sx + dx];
                                if (wx0 + wx1 > 0.0f) {
                                    int x0 = s_lo[l][1][sx + dx];
                                    int x1 = s_hi[l][1][sx + dx];
                                    acc += wy0 * (wx0 * row0[x0] + wx1 * row0[x1])
                                         + wy1 * (wx0 * row1[x0] + wx1 * row1[x1]);
                                }
                            }
                        }
                    }
                    val = acc * 0.25f;
                }
                best = fmaxf(best, val);
            }
            out[base + (size_t)cloc * CELLS + cell] = best;
        }
    }
}

extern "C" void kernel_launch(void* const* d_in, const int* in_sizes, int n_in,
                              void* d_out, int out_size)
{
    const float* f0   = (const float*)d_in[0];
    const float* f1   = (const float*)d_in[1];
    const float* f2   = (const float*)d_in[2];
    const float* f3   = (const float*)d_in[3];
    const float* rois = (const float*)d_in[4];
    int R = in_sizes[4] / 4;
    dim3 grid(R, 2);
    afp_kernel<<<grid, 256>>>(f0, f1, f2, f3, rois, (float*)d_out);
}